// round 2
// baseline (speedup 1.0000x reference)
#include <cuda_runtime.h>
#include <math.h>

#define NN 50000
#define EE 600000
#define DD 128
#define LL 4

// ---- scratch (allocation-free: __device__ globals, addressed in device code) ----
__device__ float g_X[2][NN * DD];     // ping-pong activations
__device__ float g_agg[NN * DD];      // mean-aggregated neighbor features
__device__ int   g_deg[NN];
__device__ int   g_cursor[NN];
__device__ int   g_rowptr[NN + 1];
__device__ int   g_col[EE];
__device__ float g_invdeg[NN];

// ---------------------------------------------------------------- CSR build
__global__ void k_zero() {
    int i = blockIdx.x * blockDim.x + threadIdx.x;
    if (i < NN) { g_deg[i] = 0; g_cursor[i] = 0; }
}

__global__ void k_deg(const int* __restrict__ dst) {
    int e = blockIdx.x * blockDim.x + threadIdx.x;
    if (e < EE) atomicAdd(&g_deg[dst[e]], 1);
}

// single-block exclusive scan over g_deg -> g_rowptr
__global__ void k_scan() {
    __shared__ int sd[1024];
    int t = threadIdx.x;
    int running = 0;
    for (int base = 0; base < NN; base += 1024) {
        int v = (base + t < NN) ? g_deg[base + t] : 0;
        sd[t] = v;
        __syncthreads();
        #pragma unroll
        for (int off = 1; off < 1024; off <<= 1) {
            int x = sd[t];
            int y = (t >= off) ? sd[t - off] : 0;
            __syncthreads();
            sd[t] = x + y;
            __syncthreads();
        }
        int incl = sd[t];
        if (base + t < NN) g_rowptr[base + t] = running + incl - v;
        int total = sd[1023];
        __syncthreads();            // protect sd before next chunk overwrites
        running += total;
    }
    if (t == 0) g_rowptr[NN] = running;
}

__global__ void k_invdeg() {
    int i = blockIdx.x * blockDim.x + threadIdx.x;
    if (i < NN) g_invdeg[i] = 1.0f / (float)max(g_deg[i], 1);
}

__global__ void k_fill(const int* __restrict__ src, const int* __restrict__ dst) {
    int e = blockIdx.x * blockDim.x + threadIdx.x;
    if (e < EE) {
        int d = dst[e];
        int p = atomicAdd(&g_cursor[d], 1);
        g_col[g_rowptr[d] + p] = src[e];
    }
}

// deterministic neighbor order: insertion-sort each row segment (avg deg 12)
__global__ void k_sort() {
    int i = blockIdx.x * blockDim.x + threadIdx.x;
    if (i >= NN) return;
    int beg = g_rowptr[i], end = g_rowptr[i + 1];
    for (int a = beg + 1; a < end; ++a) {
        int v = g_col[a];
        int b = a - 1;
        while (b >= beg && g_col[b] > v) { g_col[b + 1] = g_col[b]; --b; }
        g_col[b + 1] = v;
    }
}

// ---------------------------------------------------------- aggregation
// one warp per node; each lane owns one float4 (4 of 128 columns)
__global__ void k_agg(const float* __restrict__ x_in, int l) {
    int w = (blockIdx.x * blockDim.x + threadIdx.x) >> 5;
    int lane = threadIdx.x & 31;
    if (w >= NN) return;
    const float* X = (l == 0) ? x_in : g_X[(l - 1) & 1];
    int beg = g_rowptr[w], end = g_rowptr[w + 1];
    const float4* X4 = reinterpret_cast<const float4*>(X);
    float4 acc = make_float4(0.f, 0.f, 0.f, 0.f);
    for (int e = beg; e < end; ++e) {
        int s = g_col[e];
        float4 v = X4[(size_t)s * 32 + lane];
        acc.x += v.x; acc.y += v.y; acc.z += v.z; acc.w += v.w;
    }
    float inv = g_invdeg[w];
    acc.x *= inv; acc.y *= inv; acc.z *= inv; acc.w *= inv;
    reinterpret_cast<float4*>(g_agg)[(size_t)w * 32 + lane] = acc;
}

// ---------------------------------------------------------------- GEMM
// C[r,n] = sum_k X[r,k]*Wroot[k,n] + sum_k agg[r,k]*Wrel[k,n] + bias[n], then ELU.
// Block tile 128x128, K streamed in 16-chunks over two phases.
// 256 threads, 8x8 register tile per thread.
__global__ __launch_bounds__(256) void k_gemm(
    const float* __restrict__ x_in,
    const float* __restrict__ W1, const float* __restrict__ W2,
    const float* __restrict__ bias, float* __restrict__ final_out, int l)
{
    __shared__ float As[16][128];   // [k][m]
    __shared__ float Bs[16][128];   // [k][n]

    const float* A1 = (l == 0) ? x_in : g_X[(l - 1) & 1];  // X (root path)
    const float* A2 = g_agg;                               // mean-agg (rel path)
    float* Cout = (l == LL - 1) ? final_out : g_X[l & 1];

    int tid = threadIdx.x;
    int tx = tid & 15;              // output-col group (8 cols)
    int ty = tid >> 4;              // output-row group (8 rows)
    int rowBase = blockIdx.x * 128;

    float acc[8][8];
    #pragma unroll
    for (int i = 0; i < 8; ++i)
        #pragma unroll
        for (int j = 0; j < 8; ++j) acc[i][j] = 0.f;

    #pragma unroll
    for (int phase = 0; phase < 2; ++phase) {
        const float* A = phase ? A2 : A1;
        const float* W = phase ? W2 : W1;
        for (int k0 = 0; k0 < 128; k0 += 16) {
            // load A tile (transpose to [k][m]); 512 float4 slots, 2 per thread
            #pragma unroll
            for (int s0 = 0; s0 < 2; ++s0) {
                int s = tid * 2 + s0;
                int r = s >> 2, kk4 = s & 3;
                int row = rowBase + r;
                if (row >= NN) row = NN - 1;     // clamp; results masked at store
                float4 v = *reinterpret_cast<const float4*>(
                    &A[(size_t)row * DD + k0 + kk4 * 4]);
                As[kk4 * 4 + 0][r] = v.x;
                As[kk4 * 4 + 1][r] = v.y;
                As[kk4 * 4 + 2][r] = v.z;
                As[kk4 * 4 + 3][r] = v.w;
            }
            // load W tile [16][128]
            #pragma unroll
            for (int s0 = 0; s0 < 2; ++s0) {
                int s = tid * 2 + s0;
                int kk = s >> 5, n4 = s & 31;
                *reinterpret_cast<float4*>(&Bs[kk][n4 * 4]) =
                    *reinterpret_cast<const float4*>(&W[(size_t)(k0 + kk) * DD + n4 * 4]);
            }
            __syncthreads();
            #pragma unroll
            for (int kk = 0; kk < 16; ++kk) {
                float a[8], b[8];
                *reinterpret_cast<float4*>(&a[0]) = *reinterpret_cast<const float4*>(&As[kk][ty * 8]);
                *reinterpret_cast<float4*>(&a[4]) = *reinterpret_cast<const float4*>(&As[kk][ty * 8 + 4]);
                *reinterpret_cast<float4*>(&b[0]) = *reinterpret_cast<const float4*>(&Bs[kk][tx * 8]);
                *reinterpret_cast<float4*>(&b[4]) = *reinterpret_cast<const float4*>(&Bs[kk][tx * 8 + 4]);
                #pragma unroll
                for (int i = 0; i < 8; ++i)
                    #pragma unroll
                    for (int j = 0; j < 8; ++j)
                        acc[i][j] += a[i] * b[j];
            }
            __syncthreads();
        }
    }

    // epilogue: bias + ELU + store
    float bv[8];
    #pragma unroll
    for (int j = 0; j < 8; ++j) bv[j] = bias[tx * 8 + j];

    #pragma unroll
    for (int i = 0; i < 8; ++i) {
        int row = rowBase + ty * 8 + i;
        if (row < NN) {
            float o[8];
            #pragma unroll
            for (int j = 0; j < 8; ++j) {
                float v = acc[i][j] + bv[j];
                o[j] = (v > 0.f) ? v : expm1f(v);
            }
            float* dstp = &Cout[(size_t)row * DD + tx * 8];
            *reinterpret_cast<float4*>(dstp)     = *reinterpret_cast<float4*>(&o[0]);
            *reinterpret_cast<float4*>(dstp + 4) = *reinterpret_cast<float4*>(&o[4]);
        }
    }
}

// ---------------------------------------------------------------- launch
extern "C" void kernel_launch(void* const* d_in, const int* in_sizes, int n_in,
                              void* d_out, int out_size) {
    const float* node_embedding = (const float*)d_in[0];   // [N, D]
    const int*   edge_index     = (const int*)d_in[1];     // [2, E] row-major
    const float* Ws_rel         = (const float*)d_in[2];   // [L, D, D]
    const float* bs_rel         = (const float*)d_in[3];   // [L, D]
    const float* Ws_root        = (const float*)d_in[4];   // [L, D, D]
    float* out = (float*)d_out;

    const int* src = edge_index;
    const int* dst = edge_index + EE;

    // CSR build (replayed inside the graph each launch; deterministic via k_sort)
    k_zero<<<(NN + 255) / 256, 256>>>();
    k_deg<<<(EE + 255) / 256, 256>>>(dst);
    k_scan<<<1, 1024>>>();
    k_invdeg<<<(NN + 255) / 256, 256>>>();
    k_fill<<<(EE + 255) / 256, 256>>>(src, dst);
    k_sort<<<(NN + 255) / 256, 256>>>();

    int aggBlocks  = (NN * 32 + 255) / 256;
    int gemmBlocks = (NN + 127) / 128;

    for (int l = 0; l < LL; ++l) {
        k_agg<<<aggBlocks, 256>>>(node_embedding, l);
        k_gemm<<<gemmBlocks, 256>>>(
            node_embedding,
            Ws_root + (size_t)l * DD * DD,
            Ws_rel  + (size_t)l * DD * DD,
            bs_rel  + (size_t)l * DD,
            out, l);
    }
}

// round 3
// speedup vs baseline: 1.0634x; 1.0634x over previous
#include <cuda_runtime.h>
#include <math.h>

#define NN 50000
#define EE 600000
#define DD 128
#define LL 4
typedef unsigned long long ull;

// ---- scratch (allocation-free: __device__ globals) ----
__device__ float g_X[2][NN * DD];
__device__ float g_agg[NN * DD];
__device__ int   g_deg[NN];
__device__ int   g_cursor[NN];
__device__ int   g_rowptr[NN + 1];
__device__ int   g_col[EE];
__device__ float g_invdeg[NN];
__device__ int   g_part[256];       // block partial sums (196 used)
__device__ int   g_partscan[256];

// ---------------------------------------------------------------- CSR build
__global__ void k_zero() {
    int i = blockIdx.x * blockDim.x + threadIdx.x;
    if (i < NN) { g_deg[i] = 0; g_cursor[i] = 0; }
}

__global__ void k_deg(const int* __restrict__ dst) {
    int e = blockIdx.x * blockDim.x + threadIdx.x;
    if (e < EE) atomicAdd(&g_deg[dst[e]], 1);
}

// phase 1: per-block sum of 256 degrees (+ fused invdeg)
__global__ void k_s1() {
    __shared__ int sm[256];
    int t = threadIdx.x;
    int i = blockIdx.x * 256 + t;
    int v = (i < NN) ? g_deg[i] : 0;
    if (i < NN) g_invdeg[i] = 1.0f / (float)max(v, 1);
    sm[t] = v;
    __syncthreads();
    #pragma unroll
    for (int off = 128; off > 0; off >>= 1) {
        if (t < off) sm[t] += sm[t + off];
        __syncthreads();
    }
    if (t == 0) g_part[blockIdx.x] = sm[0];
}

// phase 2: one block scans the 196 partials (exclusive)
__global__ void k_s2(int nblk) {
    __shared__ int sm[256];
    int t = threadIdx.x;
    int v = (t < nblk) ? g_part[t] : 0;
    sm[t] = v;
    __syncthreads();
    #pragma unroll
    for (int off = 1; off < 256; off <<= 1) {
        int x = sm[t];
        int y = (t >= off) ? sm[t - off] : 0;
        __syncthreads();
        sm[t] = x + y;
        __syncthreads();
    }
    if (t < nblk) g_partscan[t] = sm[t] - v;
    if (t == 0) g_rowptr[NN] = EE;
}

// phase 3: per-block exclusive scan + offset -> rowptr
__global__ void k_s3() {
    __shared__ int sm[256];
    int t = threadIdx.x;
    int i = blockIdx.x * 256 + t;
    int v = (i < NN) ? g_deg[i] : 0;
    sm[t] = v;
    __syncthreads();
    #pragma unroll
    for (int off = 1; off < 256; off <<= 1) {
        int x = sm[t];
        int y = (t >= off) ? sm[t - off] : 0;
        __syncthreads();
        sm[t] = x + y;
        __syncthreads();
    }
    if (i < NN) g_rowptr[i] = g_partscan[blockIdx.x] + sm[t] - v;
}

__global__ void k_fill(const int* __restrict__ src, const int* __restrict__ dst) {
    int e = blockIdx.x * blockDim.x + threadIdx.x;
    if (e < EE) {
        int d = dst[e];
        int p = atomicAdd(&g_cursor[d], 1);
        g_col[g_rowptr[d] + p] = src[e];
    }
}

// deterministic neighbor order: insertion-sort each row segment (avg deg 12)
__global__ void k_sort() {
    int i = blockIdx.x * blockDim.x + threadIdx.x;
    if (i >= NN) return;
    int beg = g_rowptr[i], end = g_rowptr[i + 1];
    for (int a = beg + 1; a < end; ++a) {
        int v = g_col[a];
        int b = a - 1;
        while (b >= beg && g_col[b] > v) { g_col[b + 1] = g_col[b]; --b; }
        g_col[b + 1] = v;
    }
}

// ---------------------------------------------------------- aggregation
// one warp per node; each lane owns one float4; edge loop unrolled x4 for MLP
__global__ void k_agg(const float* __restrict__ x_in, int l) {
    int w = (blockIdx.x * blockDim.x + threadIdx.x) >> 5;
    int lane = threadIdx.x & 31;
    if (w >= NN) return;
    const float* X = (l == 0) ? x_in : g_X[(l - 1) & 1];
    int beg = g_rowptr[w], end = g_rowptr[w + 1];
    const float4* X4 = reinterpret_cast<const float4*>(X);
    float4 acc = make_float4(0.f, 0.f, 0.f, 0.f);
    int e = beg;
    for (; e + 3 < end; e += 4) {
        int s0 = g_col[e], s1 = g_col[e + 1], s2 = g_col[e + 2], s3 = g_col[e + 3];
        float4 v0 = X4[(size_t)s0 * 32 + lane];
        float4 v1 = X4[(size_t)s1 * 32 + lane];
        float4 v2 = X4[(size_t)s2 * 32 + lane];
        float4 v3 = X4[(size_t)s3 * 32 + lane];
        acc.x += v0.x + v1.x + v2.x + v3.x;
        acc.y += v0.y + v1.y + v2.y + v3.y;
        acc.z += v0.z + v1.z + v2.z + v3.z;
        acc.w += v0.w + v1.w + v2.w + v3.w;
    }
    for (; e < end; ++e) {
        float4 v = X4[(size_t)g_col[e] * 32 + lane];
        acc.x += v.x; acc.y += v.y; acc.z += v.z; acc.w += v.w;
    }
    float inv = g_invdeg[w];
    acc.x *= inv; acc.y *= inv; acc.z *= inv; acc.w *= inv;
    reinterpret_cast<float4*>(g_agg)[(size_t)w * 32 + lane] = acc;
}

// ---------------------------------------------------------------- GEMM (f32x2)
// C[r,n] = X@Wroot + agg@Wrel + bias, then ELU.
// 128x128 block tile, K-chunk 32, 256 threads, 8x8 thread tile as 8x4 f32x2 pairs.
__global__ __launch_bounds__(256, 2) void k_gemm(
    const float* __restrict__ x_in,
    const float* __restrict__ W1, const float* __restrict__ W2,
    const float* __restrict__ bias, float* __restrict__ final_out, int l)
{
    __shared__ float As[32][129];   // [k][m], padded for conflict-free transpose
    __shared__ float Bs[32][128];   // [k][n]

    const float* A1 = (l == 0) ? x_in : g_X[(l - 1) & 1];
    const float* A2 = g_agg;
    float* Cout = (l == LL - 1) ? final_out : g_X[l & 1];

    int tid = threadIdx.x;
    int tx = tid & 15;              // col group (8 cols = 4 f32x2 pairs)
    int ty = tid >> 4;              // row group (8 rows)
    int rowBase = blockIdx.x * 128;

    ull acc2[8][4];
    #pragma unroll
    for (int i = 0; i < 8; ++i)
        #pragma unroll
        for (int j = 0; j < 4; ++j) acc2[i][j] = 0ULL;

    #pragma unroll
    for (int phase = 0; phase < 2; ++phase) {
        const float* A = phase ? A2 : A1;
        const float* W = phase ? W2 : W1;
        #pragma unroll
        for (int k0 = 0; k0 < 128; k0 += 32) {
            // A tile: 128 rows x 32 k -> As[k][m] (transposed)
            #pragma unroll
            for (int s0 = 0; s0 < 4; ++s0) {
                int s = tid + 256 * s0;      // 0..1023 float4 slots
                int r = s >> 3;              // row 0..127
                int kk4 = s & 7;             // float4 within 32-k chunk
                int row = rowBase + r;
                if (row >= NN) row = NN - 1;
                float4 v = *reinterpret_cast<const float4*>(
                    &A[(size_t)row * DD + k0 + kk4 * 4]);
                As[kk4 * 4 + 0][r] = v.x;
                As[kk4 * 4 + 1][r] = v.y;
                As[kk4 * 4 + 2][r] = v.z;
                As[kk4 * 4 + 3][r] = v.w;
            }
            // W tile: 32 k x 128 n
            #pragma unroll
            for (int s0 = 0; s0 < 4; ++s0) {
                int s = tid + 256 * s0;
                int kk = s >> 5;             // 0..31
                int n4 = s & 31;
                *reinterpret_cast<float4*>(&Bs[kk][n4 * 4]) =
                    *reinterpret_cast<const float4*>(&W[(size_t)(k0 + kk) * DD + n4 * 4]);
            }
            __syncthreads();
            #pragma unroll
            for (int kk = 0; kk < 32; ++kk) {
                float a[8];
                #pragma unroll
                for (int i = 0; i < 8; ++i) a[i] = As[kk][ty * 8 + i];
                ull a2[8];
                #pragma unroll
                for (int i = 0; i < 8; ++i)
                    asm("mov.b64 %0, {%1, %1};" : "=l"(a2[i]) : "f"(a[i]));
                ull b2[4];
                const ull* bp = reinterpret_cast<const ull*>(&Bs[kk][tx * 8]);
                #pragma unroll
                for (int j = 0; j < 4; ++j) b2[j] = bp[j];
                #pragma unroll
                for (int i = 0; i < 8; ++i)
                    #pragma unroll
                    for (int j = 0; j < 4; ++j)
                        asm("fma.rn.f32x2 %0, %1, %2, %3;"
                            : "=l"(acc2[i][j])
                            : "l"(a2[i]), "l"(b2[j]), "l"(acc2[i][j]));
            }
            __syncthreads();
        }
    }

    // epilogue: bias + ELU + store
    float bv[8];
    #pragma unroll
    for (int j = 0; j < 8; ++j) bv[j] = bias[tx * 8 + j];

    #pragma unroll
    for (int i = 0; i < 8; ++i) {
        int row = rowBase + ty * 8 + i;
        if (row < NN) {
            float o[8];
            #pragma unroll
            for (int j = 0; j < 4; ++j) {
                float lo, hi;
                asm("mov.b64 {%0, %1}, %2;" : "=f"(lo), "=f"(hi) : "l"(acc2[i][j]));
                float v0 = lo + bv[j * 2];
                float v1 = hi + bv[j * 2 + 1];
                o[j * 2]     = (v0 > 0.f) ? v0 : expm1f(v0);
                o[j * 2 + 1] = (v1 > 0.f) ? v1 : expm1f(v1);
            }
            float* dstp = &Cout[(size_t)row * DD + tx * 8];
            *reinterpret_cast<float4*>(dstp)     = *reinterpret_cast<float4*>(&o[0]);
            *reinterpret_cast<float4*>(dstp + 4) = *reinterpret_cast<float4*>(&o[4]);
        }
    }
}

// ---------------------------------------------------------------- launch
extern "C" void kernel_launch(void* const* d_in, const int* in_sizes, int n_in,
                              void* d_out, int out_size) {
    const float* node_embedding = (const float*)d_in[0];
    const int*   edge_index     = (const int*)d_in[1];
    const float* Ws_rel         = (const float*)d_in[2];
    const float* bs_rel         = (const float*)d_in[3];
    const float* Ws_root        = (const float*)d_in[4];
    float* out = (float*)d_out;

    const int* src = edge_index;
    const int* dst = edge_index + EE;

    int nScanBlk = (NN + 255) / 256;   // 196

    k_zero<<<nScanBlk, 256>>>();
    k_deg<<<(EE + 255) / 256, 256>>>(dst);
    k_s1<<<nScanBlk, 256>>>();
    k_s2<<<1, 256>>>(nScanBlk);
    k_s3<<<nScanBlk, 256>>>();
    k_fill<<<(EE + 255) / 256, 256>>>(src, dst);
    k_sort<<<nScanBlk, 256>>>();

    int aggBlocks  = (NN * 32 + 255) / 256;
    int gemmBlocks = (NN + 127) / 128;

    for (int l = 0; l < LL; ++l) {
        k_agg<<<aggBlocks, 256>>>(node_embedding, l);
        k_gemm<<<gemmBlocks, 256>>>(
            node_embedding,
            Ws_root + (size_t)l * DD * DD,
            Ws_rel  + (size_t)l * DD * DD,
            bs_rel  + (size_t)l * DD,
            out, l);
    }
}

// round 10
// speedup vs baseline: 1.3746x; 1.2927x over previous
#include <cuda_runtime.h>
#include <cuda_bf16.h>
#include <math.h>
#include <stdint.h>

#define NN 50000
#define EE 600000
#define DD 128
#define LL 4

// ---- scratch (allocation-free __device__ globals) ----
// A operand, bf16 hi/lo: cols 0-127 = X, cols 128-255 = mean-agg
__device__ __nv_bfloat16 g_Ah[(size_t)NN * 256];
__device__ __nv_bfloat16 g_Al[(size_t)NN * 256];
// B operand per layer: B[n][k] = Wfull[k][n], k<128 -> Wroot, k>=128 -> Wrel
__device__ __nv_bfloat16 g_Bh[LL * 128 * 256];
__device__ __nv_bfloat16 g_Bl[LL * 128 * 256];
__device__ int   g_deg[NN];
__device__ int   g_cursor[NN];
__device__ int   g_rowptr[NN + 1];
__device__ int   g_col[EE];
__device__ float g_invdeg[NN];
__device__ int   g_part[256];
__device__ int   g_partscan[256];

// ---------------- small helpers ----------------
__device__ __forceinline__ uint32_t smem_u32(const void* p) {
    uint32_t a;
    asm("{ .reg .u64 t; cvta.to.shared.u64 t, %1; cvt.u32.u64 %0, t; }" : "=r"(a) : "l"(p));
    return a;
}
__device__ __forceinline__ float2 bf2_to_f2(uint32_t u) {
    __nv_bfloat162 b = *reinterpret_cast<__nv_bfloat162*>(&u);
    return make_float2(__bfloat162float(b.x), __bfloat162float(b.y));
}
__device__ __forceinline__ void split_bf16(float v, unsigned short& hi, unsigned short& lo) {
    __nv_bfloat16 h = __float2bfloat16_rn(v);
    __nv_bfloat16 l = __float2bfloat16_rn(v - __bfloat162float(h));
    hi = *reinterpret_cast<unsigned short*>(&h);
    lo = *reinterpret_cast<unsigned short*>(&l);
}

// ---------------------------------------------------------------- CSR build
__global__ void k_zero() {
    int i = blockIdx.x * blockDim.x + threadIdx.x;
    if (i < NN) { g_deg[i] = 0; g_cursor[i] = 0; }
}
__global__ void k_deg(const int* __restrict__ dst) {
    int e = blockIdx.x * blockDim.x + threadIdx.x;
    if (e < EE) atomicAdd(&g_deg[dst[e]], 1);
}
__global__ void k_s1() {
    __shared__ int sm[256];
    int t = threadIdx.x;
    int i = blockIdx.x * 256 + t;
    int v = (i < NN) ? g_deg[i] : 0;
    if (i < NN) g_invdeg[i] = 1.0f / (float)max(v, 1);
    sm[t] = v;
    __syncthreads();
    #pragma unroll
    for (int off = 128; off > 0; off >>= 1) {
        if (t < off) sm[t] += sm[t + off];
        __syncthreads();
    }
    if (t == 0) g_part[blockIdx.x] = sm[0];
}
__global__ void k_s2(int nblk) {
    __shared__ int sm[256];
    int t = threadIdx.x;
    int v = (t < nblk) ? g_part[t] : 0;
    sm[t] = v;
    __syncthreads();
    #pragma unroll
    for (int off = 1; off < 256; off <<= 1) {
        int x = sm[t];
        int y = (t >= off) ? sm[t - off] : 0;
        __syncthreads();
        sm[t] = x + y;
        __syncthreads();
    }
    if (t < nblk) g_partscan[t] = sm[t] - v;
    if (t == 0) g_rowptr[NN] = EE;
}
__global__ void k_s3() {
    __shared__ int sm[256];
    int t = threadIdx.x;
    int i = blockIdx.x * 256 + t;
    int v = (i < NN) ? g_deg[i] : 0;
    sm[t] = v;
    __syncthreads();
    #pragma unroll
    for (int off = 1; off < 256; off <<= 1) {
        int x = sm[t];
        int y = (t >= off) ? sm[t - off] : 0;
        __syncthreads();
        sm[t] = x + y;
        __syncthreads();
    }
    if (i < NN) g_rowptr[i] = g_partscan[blockIdx.x] + sm[t] - v;
}
__global__ void k_fill(const int* __restrict__ src, const int* __restrict__ dst) {
    int e = blockIdx.x * blockDim.x + threadIdx.x;
    if (e < EE) {
        int d = dst[e];
        int p = atomicAdd(&g_cursor[d], 1);
        g_col[g_rowptr[d] + p] = src[e];
    }
}
__global__ void k_sort() {
    int i = blockIdx.x * blockDim.x + threadIdx.x;
    if (i >= NN) return;
    int beg = g_rowptr[i], end = g_rowptr[i + 1];
    for (int a = beg + 1; a < end; ++a) {
        int v = g_col[a];
        int b = a - 1;
        while (b >= beg && g_col[b] > v) { g_col[b + 1] = g_col[b]; --b; }
        g_col[b + 1] = v;
    }
}

// ---------------------------------------------------------------- converts
__global__ void k_convA(const float* __restrict__ x) {
    int idx = blockIdx.x * blockDim.x + threadIdx.x;   // 0 .. NN*32-1
    if (idx >= NN * 32) return;
    int i4 = idx * 4;
    int row = i4 >> 7, c = i4 & 127;
    float4 v = *reinterpret_cast<const float4*>(&x[i4]);
    unsigned short h[4], l[4];
    split_bf16(v.x, h[0], l[0]);
    split_bf16(v.y, h[1], l[1]);
    split_bf16(v.z, h[2], l[2]);
    split_bf16(v.w, h[3], l[3]);
    size_t o = (size_t)row * 256 + c;
    *reinterpret_cast<uint2*>(&g_Ah[o]) = make_uint2((uint32_t)h[0] | ((uint32_t)h[1] << 16),
                                                     (uint32_t)h[2] | ((uint32_t)h[3] << 16));
    *reinterpret_cast<uint2*>(&g_Al[o]) = make_uint2((uint32_t)l[0] | ((uint32_t)l[1] << 16),
                                                     (uint32_t)l[2] | ((uint32_t)l[3] << 16));
}

__global__ void k_convW(const float* __restrict__ Wroot, const float* __restrict__ Wrel) {
    int idx = blockIdx.x * blockDim.x + threadIdx.x;   // LL*256*128
    if (idx >= LL * 256 * 128) return;
    int l = idx >> 15;
    int r = idx & 32767;
    int k = r >> 7, n = r & 127;
    float w = (k < 128) ? Wroot[l * 16384 + k * 128 + n]
                        : Wrel[l * 16384 + (k - 128) * 128 + n];
    unsigned short h, lo;
    split_bf16(w, h, lo);
    size_t o = (size_t)l * 32768 + (size_t)n * 256 + k;
    *reinterpret_cast<unsigned short*>(&g_Bh[o]) = h;
    *reinterpret_cast<unsigned short*>(&g_Bl[o]) = lo;
}

// ---------------------------------------------------------- aggregation
__global__ void k_agg() {
    int w = (blockIdx.x * blockDim.x + threadIdx.x) >> 5;
    int lane = threadIdx.x & 31;
    if (w >= NN) return;
    int beg = g_rowptr[w], end = g_rowptr[w + 1];
    float a0 = 0.f, a1 = 0.f, a2 = 0.f, a3 = 0.f;
    for (int e = beg; e < end; ++e) {
        int s = g_col[e];
        size_t o = (size_t)s * 256 + lane * 4;
        uint2 hv = *reinterpret_cast<const uint2*>(&g_Ah[o]);
        uint2 lv = *reinterpret_cast<const uint2*>(&g_Al[o]);
        float2 h0 = bf2_to_f2(hv.x), h1 = bf2_to_f2(hv.y);
        float2 l0 = bf2_to_f2(lv.x), l1 = bf2_to_f2(lv.y);
        a0 += h0.x + l0.x; a1 += h0.y + l0.y;
        a2 += h1.x + l1.x; a3 += h1.y + l1.y;
    }
    float inv = g_invdeg[w];
    a0 *= inv; a1 *= inv; a2 *= inv; a3 *= inv;
    unsigned short h[4], l[4];
    split_bf16(a0, h[0], l[0]);
    split_bf16(a1, h[1], l[1]);
    split_bf16(a2, h[2], l[2]);
    split_bf16(a3, h[3], l[3]);
    size_t o = (size_t)w * 256 + 128 + lane * 4;
    *reinterpret_cast<uint2*>(&g_Ah[o]) = make_uint2((uint32_t)h[0] | ((uint32_t)h[1] << 16),
                                                     (uint32_t)h[2] | ((uint32_t)h[3] << 16));
    *reinterpret_cast<uint2*>(&g_Al[o]) = make_uint2((uint32_t)l[0] | ((uint32_t)l[1] << 16),
                                                     (uint32_t)l[2] | ((uint32_t)l[3] << 16));
}

// ---------------------------------------------------------------- mma.sync GEMM
// D[128,128] = A(hi+lo)[128,256] x B(hi+lo)[128,256]^T, 3 products, fp32 acc.
// 8 warps: warp (w&3) -> 32-row group, (w>>2) -> 64-col group.
// K chunked by 64 into SW128-swizzled smem; ldmatrix + mma.sync m16n8k16 bf16.
#define SM_AH    0
#define SM_AL    16384
#define SM_BH    32768
#define SM_BL    49152
#define SM_TOTAL 65536

// load a 128x64 bf16 tile (rows rowBase.., cols k0..k0+63) into swizzled smem
__device__ __forceinline__ void load_tile(char* smem, int smOff,
                                          const __nv_bfloat16* __restrict__ gbase,
                                          int rowBase, int rowMax, int k0, int tid) {
    #pragma unroll
    for (int i = 0; i < 4; ++i) {
        int s = tid + 256 * i;          // 0..1023 16-byte slots
        int r = s >> 3;
        int c8 = s & 7;
        int row = rowBase + r;
        if (row > rowMax) row = rowMax;
        uint4 v = *reinterpret_cast<const uint4*>(&gbase[(size_t)row * 256 + k0 + c8 * 8]);
        uint32_t byte = r * 128 + c8 * 16;
        uint32_t sw = byte ^ ((byte >> 3) & 0x70);
        *reinterpret_cast<uint4*>(smem + smOff + sw) = v;
    }
}
__device__ __forceinline__ void load_tileW(char* smem, int smOff,
                                           const __nv_bfloat16* __restrict__ gbase,
                                           int k0, int tid) {
    #pragma unroll
    for (int i = 0; i < 4; ++i) {
        int s = tid + 256 * i;
        int r = s >> 3;
        int c8 = s & 7;
        uint4 v = *reinterpret_cast<const uint4*>(&gbase[(size_t)r * 256 + k0 + c8 * 8]);
        uint32_t byte = r * 128 + c8 * 16;
        uint32_t sw = byte ^ ((byte >> 3) & 0x70);
        *reinterpret_cast<uint4*>(smem + smOff + sw) = v;
    }
}

__device__ __forceinline__ void ldsm4(uint32_t* r, uint32_t addr) {
    asm volatile("ldmatrix.sync.aligned.m8n8.x4.shared.b16 {%0,%1,%2,%3}, [%4];"
                 : "=r"(r[0]), "=r"(r[1]), "=r"(r[2]), "=r"(r[3]) : "r"(addr));
}
__device__ __forceinline__ void mma16816(float* c, const uint32_t* a,
                                         uint32_t b0, uint32_t b1) {
    asm volatile(
        "mma.sync.aligned.m16n8k16.row.col.f32.bf16.bf16.f32 "
        "{%0,%1,%2,%3}, {%4,%5,%6,%7}, {%8,%9}, {%0,%1,%2,%3};"
        : "+f"(c[0]), "+f"(c[1]), "+f"(c[2]), "+f"(c[3])
        : "r"(a[0]), "r"(a[1]), "r"(a[2]), "r"(a[3]), "r"(b0), "r"(b1));
}

__global__ __launch_bounds__(256) void k_gemm(
    const float* __restrict__ bias, float* __restrict__ final_out, int l)
{
    extern __shared__ char smem[];
    uint32_t smem_base = smem_u32(smem);
    int tid = threadIdx.x;
    int wid = tid >> 5;
    int lane = tid & 31;
    int rowBase = blockIdx.x * 128;
    int mbase = (wid & 3) * 32;     // warp's 32-row group within tile
    int nbase = (wid >> 2) * 64;    // warp's 64-col group

    const __nv_bfloat16* Bh = g_Bh + (size_t)l * 32768;
    const __nv_bfloat16* Bl = g_Bl + (size_t)l * 32768;

    float acc[2][8][4];
    #pragma unroll
    for (int i = 0; i < 2; ++i)
        #pragma unroll
        for (int j = 0; j < 8; ++j)
            #pragma unroll
            for (int q = 0; q < 4; ++q) acc[i][j][q] = 0.f;

    // per-lane ldmatrix offset pieces (row-within-16, k-half)
    int lrow = lane & 15;
    int lkb = (lane >> 4) * 16;     // 0 or 16 bytes (k 0-7 / 8-15)

    #pragma unroll 1
    for (int chunk = 0; chunk < 4; ++chunk) {
        int k0 = chunk * 64;
        load_tile (smem, SM_AH, g_Ah, rowBase, NN - 1, k0, tid);
        load_tile (smem, SM_AL, g_Al, rowBase, NN - 1, k0, tid);
        load_tileW(smem, SM_BH, Bh, k0, tid);
        load_tileW(smem, SM_BL, Bl, k0, tid);
        __syncthreads();

        #pragma unroll
        for (int kk = 0; kk < 4; ++kk) {
            int cb = kk * 32 + lkb;     // byte offset within 128B row
            uint32_t ah[2][4], al[2][4];
            #pragma unroll
            for (int mt = 0; mt < 2; ++mt) {
                uint32_t byte = (uint32_t)(mbase + mt * 16 + lrow) * 128 + cb;
                uint32_t sw = byte ^ ((byte >> 3) & 0x70);
                ldsm4(ah[mt], smem_base + SM_AH + sw);
                ldsm4(al[mt], smem_base + SM_AL + sw);
            }
            uint32_t bh[4][4], bl[4][4];
            #pragma unroll
            for (int nt = 0; nt < 4; ++nt) {
                uint32_t byte = (uint32_t)(nbase + nt * 16 + lrow) * 128 + cb;
                uint32_t sw = byte ^ ((byte >> 3) & 0x70);
                ldsm4(bh[nt], smem_base + SM_BH + sw);
                ldsm4(bl[nt], smem_base + SM_BL + sw);
            }
            #pragma unroll
            for (int mt = 0; mt < 2; ++mt) {
                #pragma unroll
                for (int nj = 0; nj < 8; ++nj) {
                    int nt = nj >> 1, odd = nj & 1;
                    // ldmatrix.x4 on n16xk16: r0=n0-7/k0-7, r1=n8-15/k0-7,
                    // r2=n0-7/k8-15, r3=n8-15/k8-15
                    mma16816(acc[mt][nj], ah[mt], bh[nt][odd], bh[nt][2 + odd]);
                    mma16816(acc[mt][nj], ah[mt], bl[nt][odd], bl[nt][2 + odd]);
                    mma16816(acc[mt][nj], al[mt], bh[nt][odd], bh[nt][2 + odd]);
                }
            }
        }
        __syncthreads();
    }

    // epilogue: bias + ELU + store (final fp32, else split hi/lo bf16)
    int group = lane >> 2;          // 0..7
    int tig = lane & 3;             // 0..3
    #pragma unroll
    for (int mt = 0; mt < 2; ++mt) {
        #pragma unroll
        for (int half = 0; half < 2; ++half) {
            int row = rowBase + mbase + mt * 16 + half * 8 + group;
            if (row >= NN) continue;
            #pragma unroll
            for (int nj = 0; nj < 8; ++nj) {
                int col = nbase + nj * 8 + tig * 2;
                float v0 = acc[mt][nj][half * 2]     + bias[col];
                float v1 = acc[mt][nj][half * 2 + 1] + bias[col + 1];
                v0 = (v0 > 0.f) ? v0 : expm1f(v0);
                v1 = (v1 > 0.f) ? v1 : expm1f(v1);
                if (l == LL - 1) {
                    float2 o = make_float2(v0, v1);
                    *reinterpret_cast<float2*>(&final_out[(size_t)row * 128 + col]) = o;
                } else {
                    unsigned short h0, l0, h1, l1;
                    split_bf16(v0, h0, l0);
                    split_bf16(v1, h1, l1);
                    size_t o = (size_t)row * 256 + col;
                    *reinterpret_cast<uint32_t*>(&g_Ah[o]) = (uint32_t)h0 | ((uint32_t)h1 << 16);
                    *reinterpret_cast<uint32_t*>(&g_Al[o]) = (uint32_t)l0 | ((uint32_t)l1 << 16);
                }
            }
        }
    }
}

// ---------------------------------------------------------------- launch
extern "C" void kernel_launch(void* const* d_in, const int* in_sizes, int n_in,
                              void* d_out, int out_size) {
    const float* node_embedding = (const float*)d_in[0];
    const int*   edge_index     = (const int*)d_in[1];
    const float* Ws_rel         = (const float*)d_in[2];
    const float* bs_rel         = (const float*)d_in[3];
    const float* Ws_root        = (const float*)d_in[4];
    float* out = (float*)d_out;

    const int* src = edge_index;
    const int* dst = edge_index + EE;

    cudaFuncSetAttribute(k_gemm, cudaFuncAttributeMaxDynamicSharedMemorySize, SM_TOTAL);

    int nScanBlk = (NN + 255) / 256;   // 196

    k_zero<<<nScanBlk, 256>>>();
    k_deg<<<(EE + 255) / 256, 256>>>(dst);
    k_s1<<<nScanBlk, 256>>>();
    k_s2<<<1, 256>>>(nScanBlk);
    k_s3<<<nScanBlk, 256>>>();
    k_fill<<<(EE + 255) / 256, 256>>>(src, dst);
    k_sort<<<nScanBlk, 256>>>();
    k_convA<<<(NN * 32 + 255) / 256, 256>>>(node_embedding);
    k_convW<<<(LL * 256 * 128 + 255) / 256, 256>>>(Ws_root, Ws_rel);

    int aggBlocks  = (NN * 32 + 255) / 256;
    int gemmBlocks = (NN + 127) / 128;   // 391

    for (int l = 0; l < LL; ++l) {
        k_agg<<<aggBlocks, 256>>>();
        k_gemm<<<gemmBlocks, 256, SM_TOTAL>>>(bs_rel + (size_t)l * DD, out, l);
    }
}